// round 15
// baseline (speedup 1.0000x reference)
#include <cuda_runtime.h>
#include <cuda_fp16.h>
#include <math.h>

#define N_NODES 50000
#define N_EDGES 800000
#define D 128
#define CAP 128                 // fixed bin capacity per node (mean deg 32, sigma 5.7)
#define GEMM_NODES 32
#define GEMM_GRID 296           // persistent: 2 blocks x 148 SMs

// Scratch (device globals: no allocation allowed in kernel_launch)
__device__ float  g_z[N_NODES * D];         // mixed accumulator
__device__ float  g_alpha[N_NODES];
__device__ float  g_Wp[D * D];              // pair-interleaved W
__device__ int    g_cnt[N_NODES];           // per-destination fill counts
__device__ int2   g_bin[N_NODES * CAP];     // (xh-byte-offset | hp<<31, val-bits)
__device__ __half g_xh[N_NODES * D];        // fp16 copy of x for the gather

__global__ void interleave_W_kernel(const float* __restrict__ W) {
    int idx = blockIdx.x * blockDim.x + threadIdx.x;
    if (idx < D * D) {
        int k2 = idx >> 8;
        int r  = idx & 255;
        int o  = r >> 1;
        int p  = r & 1;
        g_Wp[idx] = W[o * D + (k2 * 2 + p)];
    }
}

// One warp per node: alpha = sigmoid(x . theta + b) AND fp16 row conversion.
__global__ void alpha_xhalf_kernel(const float* __restrict__ x,
                                   const float* __restrict__ aw,
                                   const float* __restrict__ ab,
                                   float* __restrict__ out_alpha,
                                   int write_alpha) {
    int warp = (blockIdx.x * blockDim.x + threadIdx.x) >> 5;
    int lane = threadIdx.x & 31;
    if (warp >= N_NODES) return;
    float4 xv = *reinterpret_cast<const float4*>(x + (size_t)warp * D + lane * 4);

    __half2 h0 = __floats2half2_rn(xv.x, xv.y);
    __half2 h1 = __floats2half2_rn(xv.z, xv.w);
    uint2 packed;
    packed.x = *reinterpret_cast<unsigned*>(&h0);
    packed.y = *reinterpret_cast<unsigned*>(&h1);
    *reinterpret_cast<uint2*>(g_xh + (size_t)warp * D + lane * 4) = packed;

    float4 wv = *reinterpret_cast<const float4*>(aw + lane * 4);
    float s = xv.x * wv.x + xv.y * wv.y + xv.z * wv.z + xv.w * wv.w;
    #pragma unroll
    for (int off = 16; off; off >>= 1) s += __shfl_xor_sync(0xffffffffu, s, off);
    if (lane == 0) {
        float a = 1.f / (1.f + expf(-(s + ab[0])));
        g_alpha[warp] = a;
        if (write_alpha) out_alpha[warp] = a;
    }
}

// Bin (col*256 | hp<<31, val): offset is the BYTE offset of the fp16 row, so
// pull needs zero address IMADs. 4 edges of each operator per thread.
__global__ void bin_kernel(const int* __restrict__ lp_rows,
                           const int* __restrict__ lp_cols,
                           const float* __restrict__ lp_vals,
                           const int* __restrict__ hp_rows,
                           const int* __restrict__ hp_cols,
                           const float* __restrict__ hp_vals) {
    int i = blockIdx.x * blockDim.x + threadIdx.x;
    if (i >= N_EDGES / 4) return;

    int4   lr = reinterpret_cast<const int4*>(lp_rows)[i];
    int4   lc = reinterpret_cast<const int4*>(lp_cols)[i];
    float4 lv = reinterpret_cast<const float4*>(lp_vals)[i];
    int4   hr = reinterpret_cast<const int4*>(hp_rows)[i];
    int4   hc = reinterpret_cast<const int4*>(hp_cols)[i];
    float4 hv = reinterpret_cast<const float4*>(hp_vals)[i];

    int    rs[8] = {lr.x, lr.y, lr.z, lr.w, hr.x, hr.y, hr.z, hr.w};
    int    cs[8] = {lc.x << 8, lc.y << 8, lc.z << 8, lc.w << 8,
                    (hc.x << 8) | (int)0x80000000, (hc.y << 8) | (int)0x80000000,
                    (hc.z << 8) | (int)0x80000000, (hc.w << 8) | (int)0x80000000};
    float  vs[8] = {lv.x, lv.y, lv.z, lv.w, hv.x, hv.y, hv.z, hv.w};

    #pragma unroll
    for (int j = 0; j < 8; j++) {
        int pos = atomicAdd(&g_cnt[rs[j]], 1);
        g_bin[(rs[j] << 7) + pos] = make_int2(cs[j], __float_as_int(vs[j]));
    }
}

// Pull-mode gather: HALF-WARP groups. Warp = 2 groups x 16 lanes; each group
// owns one node; a lane covers 8 halfs (16B) of the row. One LDG.128 + one
// SHFL pair serves TWO edges (one per group). fp32 accumulate.
__global__ void pull_kernel() {
    int warp = (blockIdx.x * blockDim.x + threadIdx.x) >> 5;
    int lane = threadIdx.x & 31;
    int gl   = lane & 15;          // lane within group
    int gsel = lane & 16;          // 0 or 16: group's shfl base
    int node = warp * 2 + (lane >> 4);
    // N_NODES even and grid sized exactly: every warp has 2 valid nodes.

    int s = node << 7;
    int deg = g_cnt[node];
    int e = s + deg;
    float a = g_alpha[node];
    float one_m_a = 1.f - a;
    const char* xbase = reinterpret_cast<const char*>(g_xh) + gl * 16;

    float a0 = 0.f, a1 = 0.f, a2 = 0.f, a3 = 0.f;
    float a4 = 0.f, a5 = 0.f, a6 = 0.f, a7 = 0.f;

    int deg_other = __shfl_xor_sync(0xffffffffu, deg, 16);
    int iters = (max(deg, deg_other) + 15) >> 4;

    for (int it = 0; it < iters; it++) {
        int chunk = it * 16;
        int myi = s + chunk + gl;
        int2 slot = (myi < e) ? g_bin[myi] : make_int2(0, 0);
        int   off  = slot.x & 0x7FFFFFFF;
        float gate = (slot.x < 0) ? one_m_a : a;
        float coef = gate * __int_as_float(slot.y);
        // group-wise remaining count; shared bound = pairwise max
        int rem_self = min(16, deg - chunk);
        if (rem_self < 0) rem_self = 0;
        int rem_other = __shfl_xor_sync(0xffffffffu, rem_self, 16);
        int cnt = max(rem_self, rem_other);

        #pragma unroll 4
        for (int j = 0; j < cnt; j++) {
            int src = gsel + j;
            int   oj = __shfl_sync(0xffffffffu, off,  src);
            float fj = __shfl_sync(0xffffffffu, coef, src);
            uint4 raw = *reinterpret_cast<const uint4*>(xbase + oj);
            float2 q0 = __half22float2(*reinterpret_cast<__half2*>(&raw.x));
            float2 q1 = __half22float2(*reinterpret_cast<__half2*>(&raw.y));
            float2 q2 = __half22float2(*reinterpret_cast<__half2*>(&raw.z));
            float2 q3 = __half22float2(*reinterpret_cast<__half2*>(&raw.w));
            a0 = fmaf(fj, q0.x, a0); a1 = fmaf(fj, q0.y, a1);
            a2 = fmaf(fj, q1.x, a2); a3 = fmaf(fj, q1.y, a3);
            a4 = fmaf(fj, q2.x, a4); a5 = fmaf(fj, q2.y, a5);
            a6 = fmaf(fj, q3.x, a6); a7 = fmaf(fj, q3.y, a7);
        }
    }
    float* zrow = g_z + (size_t)node * D + gl * 8;
    float4 r0; r0.x = a0; r0.y = a1; r0.z = a2; r0.w = a3;
    float4 r1; r1.x = a4; r1.y = a5; r1.z = a6; r1.w = a7;
    *reinterpret_cast<float4*>(zrow)     = r0;
    *reinterpret_cast<float4*>(zrow + 4) = r1;
}

// ---- packed f32x2 helpers ----
__device__ __forceinline__ void fma2(unsigned long long& acc,
                                     unsigned long long a,
                                     unsigned long long b) {
    asm("fma.rn.f32x2 %0, %1, %2, %0;" : "+l"(acc) : "l"(a), "l"(b));
}
__device__ __forceinline__ void unpack2(unsigned long long v, float& lo, float& hi) {
    asm("mov.b64 {%0, %1}, %2;" : "=f"(lo), "=f"(hi) : "l"(v));
}

// Persistent GEMM: out[n][o] = relu(sum_k z[n][k] * W[o][k] + b[o]).
extern __shared__ float g_smem[];
__global__ void gemm_relu_kernel(const float* __restrict__ bias,
                                 float* __restrict__ out) {
    float* wp_sh = g_smem;              // 128*128 floats (64 KB)
    float* z_sh  = g_smem + D * D;      // 32*128 floats (16 KB)
    int tid = threadIdx.x;
    int lane = tid & 31;
    int wrp  = tid >> 5;
    int o_base = lane * 4;
    int n0 = wrp * 4;
    const int n_tiles = (N_NODES + GEMM_NODES - 1) / GEMM_NODES;

    {
        const float4* src = reinterpret_cast<const float4*>(g_Wp);
        float4* dst = reinterpret_cast<float4*>(wp_sh);
        #pragma unroll
        for (int i = tid; i < D * D / 4; i += 256) dst[i] = src[i];
    }
    float4 bv = *reinterpret_cast<const float4*>(bias + o_base);

    for (int tile = blockIdx.x; tile < n_tiles; tile += gridDim.x) {
        int node_base = tile * GEMM_NODES;
        int nodes_here = min(GEMM_NODES, N_NODES - node_base);
        __syncthreads();
        {
            const float4* src =
                reinterpret_cast<const float4*>(g_z + (size_t)node_base * D);
            float4* dst = reinterpret_cast<float4*>(z_sh);
            int n4 = nodes_here * D / 4;
            for (int i = tid; i < n4; i += 256) dst[i] = src[i];
        }
        __syncthreads();

        const unsigned long long* z0p =
            reinterpret_cast<const unsigned long long*>(z_sh + (n0 + 0) * D);
        const unsigned long long* z1p =
            reinterpret_cast<const unsigned long long*>(z_sh + (n0 + 1) * D);
        const unsigned long long* z2p =
            reinterpret_cast<const unsigned long long*>(z_sh + (n0 + 2) * D);
        const unsigned long long* z3p =
            reinterpret_cast<const unsigned long long*>(z_sh + (n0 + 3) * D);

        unsigned long long acc[4][4];
        #pragma unroll
        for (int n = 0; n < 4; n++)
            #pragma unroll
            for (int c = 0; c < 4; c++) acc[n][c] = 0ull;

        #pragma unroll 8
        for (int k2 = 0; k2 < D / 2; k2++) {
            unsigned long long z0 = z0p[k2];
            unsigned long long z1 = z1p[k2];
            unsigned long long z2 = z2p[k2];
            unsigned long long z3 = z3p[k2];
            const float* wbase = wp_sh + k2 * 256 + o_base * 2;
            ulonglong2 wA = *reinterpret_cast<const ulonglong2*>(wbase);
            ulonglong2 wB = *reinterpret_cast<const ulonglong2*>(wbase + 4);
            fma2(acc[0][0], z0, wA.x); fma2(acc[0][1], z0, wA.y);
            fma2(acc[0][2], z0, wB.x); fma2(acc[0][3], z0, wB.y);
            fma2(acc[1][0], z1, wA.x); fma2(acc[1][1], z1, wA.y);
            fma2(acc[1][2], z1, wB.x); fma2(acc[1][3], z1, wB.y);
            fma2(acc[2][0], z2, wA.x); fma2(acc[2][1], z2, wA.y);
            fma2(acc[2][2], z2, wB.x); fma2(acc[2][3], z2, wB.y);
            fma2(acc[3][0], z3, wA.x); fma2(acc[3][1], z3, wA.y);
            fma2(acc[3][2], z3, wB.x); fma2(acc[3][3], z3, wB.y);
        }

        #pragma unroll
        for (int n = 0; n < 4; n++) {
            int node = node_base + n0 + n;
            if (node >= N_NODES) break;
            float lo, hi;
            float4 r;
            unpack2(acc[n][0], lo, hi); r.x = fmaxf(lo + hi + bv.x, 0.f);
            unpack2(acc[n][1], lo, hi); r.y = fmaxf(lo + hi + bv.y, 0.f);
            unpack2(acc[n][2], lo, hi); r.z = fmaxf(lo + hi + bv.z, 0.f);
            unpack2(acc[n][3], lo, hi); r.w = fmaxf(lo + hi + bv.w, 0.f);
            *reinterpret_cast<float4*>(out + (size_t)node * D + o_base) = r;
        }
    }
}

extern "C" void kernel_launch(void* const* d_in, const int* in_sizes, int n_in,
                              void* d_out, int out_size) {
    const float* x       = (const float*)d_in[0];
    const int*   lp_rows = (const int*)d_in[1];
    const int*   lp_cols = (const int*)d_in[2];
    const float* lp_vals = (const float*)d_in[3];
    const int*   hp_rows = (const int*)d_in[4];
    const int*   hp_cols = (const int*)d_in[5];
    const float* hp_vals = (const float*)d_in[6];
    const float* alpha_w = (const float*)d_in[7];
    const float* alpha_b = (const float*)d_in[8];
    const float* W       = (const float*)d_in[9];
    const float* bvec    = (const float*)d_in[10];
    float* out = (float*)d_out;

    int write_alpha = (out_size >= N_NODES * D + N_NODES) ? 1 : 0;

    static cudaStream_t s_side = nullptr;
    static cudaEvent_t  ev_fork = nullptr, ev_join = nullptr;
    if (!s_side) {
        cudaStreamCreateWithFlags(&s_side, cudaStreamNonBlocking);
        cudaEventCreateWithFlags(&ev_fork, cudaEventDisableTiming);
        cudaEventCreateWithFlags(&ev_join, cudaEventDisableTiming);
    }

    void* cnt_ptr = nullptr;
    cudaGetSymbolAddress(&cnt_ptr, g_cnt);

    // Fork: side stream runs x-bound kernels concurrently with edge-bound bin.
    cudaEventRecord(ev_fork, 0);
    cudaStreamWaitEvent(s_side, ev_fork, 0);

    cudaMemsetAsync(cnt_ptr, 0, N_NODES * sizeof(int), 0);
    bin_kernel<<<(N_EDGES / 4 + 255) / 256, 256>>>(
        lp_rows, lp_cols, lp_vals, hp_rows, hp_cols, hp_vals);

    interleave_W_kernel<<<(D * D + 255) / 256, 256, 0, s_side>>>(W);
    alpha_xhalf_kernel<<<(N_NODES * 32 + 255) / 256, 256, 0, s_side>>>(
        x, alpha_w, alpha_b, out + (size_t)N_NODES * D, write_alpha);

    // Join: pull needs bin (main) + alpha/xh (side).
    cudaEventRecord(ev_join, s_side);
    cudaStreamWaitEvent(0, ev_join, 0);

    // 2 nodes per warp: 25000 warps = 800000 threads / 256 = 3125 blocks.
    pull_kernel<<<(N_NODES / 2 * 32) / 256, 256>>>();

    const int smem_bytes = (D * D + GEMM_NODES * D) * (int)sizeof(float); // 81920
    cudaFuncSetAttribute(gemm_relu_kernel,
                         cudaFuncAttributeMaxDynamicSharedMemorySize, smem_bytes);
    gemm_relu_kernel<<<GEMM_GRID, 256, smem_bytes>>>(bvec, out);
}